// round 17
// baseline (speedup 1.0000x reference)
#include <cuda_runtime.h>
#include <cuda_bf16.h>
#include <cuda_fp16.h>
#include <cstdint>

#define N_NODES 100000
#define N_EDGES 3200000
#define H 128
#define N_GRAPHS 128
#define N_CLASSES 10
#define EPSBN 1e-5f
#define CAP 96                  // bucket capacity; P(deg>=96 | Poisson(32)) ~ 1e-18

// accumulator region (single memset): [BN1 2H][BN2 2H][POOL 128*128][GCNT 128]
#define OFF_BN1  0
#define OFF_BN2  (2 * H)
#define OFF_POOL (4 * H)
#define OFF_GCNT (4 * H + N_GRAPHS * H)
#define ACC_LEN  (4 * H + N_GRAPHS * H + N_GRAPHS)

// ---------------- device scratch (static, no allocation) ----------------
__device__ int   g_cur[N_NODES];                                // slot cursor -> degree
__device__ int   g_deg[N_NODES];
__device__ int   g_csrc[(size_t)N_NODES * CAP];                 // bucketed src ids
__device__ float g_dinv[N_NODES];                               // rsqrt(deg+1)
__device__ float g_rdinv[N_NODES];                              // sqrt(deg+1)
__device__ __align__(8) float2 g_dx[N_NODES];                   // {dinv, dinv*x}
__device__ __align__(16) float4 g_ax[N_NODES];                  // {aconv, x, dinv, 0}
__device__ float g_sdin[N_NODES];                               // sum dinv[s]
__device__ __align__(16) __half g_h1s[(size_t)N_NODES * H];     // dinv[i]*relu(h1) fp16
__device__ __align__(16) __half g_aggh[(size_t)N_NODES * H];    // sum_s h1s[s] fp16
__device__ __align__(8) uint2 g_w2[128 * 128];                  // [n][kword]: {hi,lo} bf16x2
__device__ float g_acc[ACC_LEN];                                // fused accumulators

// ---------------- bucketed adjacency build (single pass) ----------------

__global__ void k_fill(const int* __restrict__ src, const int* __restrict__ dst) {
    int e = blockIdx.x * blockDim.x + threadIdx.x;
    if (e >= N_EDGES) return;
    int d = dst[e];
    int slot = atomicAdd(&g_cur[d], 1);
    if (slot >= CAP) slot = CAP - 1;        // astronomically unlikely; never OOB
    g_csrc[(size_t)d * CAP + slot] = src[e];
}

// degree/dinv/rdinv/dx + fused per-graph node counting (float-exact counts)
__global__ void __launch_bounds__(1024) k_finoff(const float* __restrict__ x,
                                                 const int* __restrict__ batch) {
    __shared__ int sh[N_GRAPHS];
    int t = threadIdx.x;
    if (t < N_GRAPHS) sh[t] = 0;
    __syncthreads();
    int i = blockIdx.x * 1024 + t;
    if (i < N_NODES) {
        int dg = min(g_cur[i], CAP);
        g_deg[i] = dg;
        float dp1 = (float)(dg + 1);
        float di = rsqrtf(dp1);
        g_dinv[i]  = di;
        g_rdinv[i] = sqrtf(dp1);
        g_dx[i] = make_float2(di, di * x[i]);
        atomicAdd(&sh[batch[i]], 1);
    }
    __syncthreads();
    if (t < N_GRAPHS && sh[t])
        atomicAdd(&g_acc[OFF_GCNT + t], (float)sh[t]);
}

// ---------------- layer 1 ----------------

// warp per node: aggregation + packed node record {aconv, x, dinv, 0}
__global__ void k_gather1(const float* __restrict__ x) {
    int node = (blockIdx.x * blockDim.x + threadIdx.x) >> 5;
    int lane = threadIdx.x & 31;
    if (node >= N_NODES) return;
    int e0 = node * CAP;
    int e1 = e0 + g_deg[node];
    float a = 0.f, sd = 0.f;
    for (int e = e0 + lane; e < e1; e += 32) {
        float2 dx = __ldg(&g_dx[g_csrc[e]]);
        a  += dx.y;
        sd += dx.x;
    }
#pragma unroll
    for (int o = 16; o > 0; o >>= 1) {
        a  += __shfl_down_sync(0xffffffffu, a, o);
        sd += __shfl_down_sync(0xffffffffu, sd, o);
    }
    if (lane == 0) {
        float di = g_dinv[node];
        float xi = x[node];
        float aconv = di * a + di * di * xi;
        g_ax[node] = make_float4(aconv, xi, di, 0.f);
        g_sdin[node] = sd;
    }
}

// layer1 transform; smem-staged node records. NPB=256: 391 same-address
// collisions per BN1 feature (atomic serialization was the binding constraint)
#define NPB 256
__global__ void __launch_bounds__(H) k_layer1(const float* __restrict__ Wc1,
                                              const float* __restrict__ bc1,
                                              const float* __restrict__ Wl1,
                                              const float* __restrict__ bl1) {
    __shared__ float4 sax[NPB];
    int f = threadIdx.x;
    int i0 = blockIdx.x * NPB;
#pragma unroll
    for (int j = 0; j < NPB / H; j++) {
        int r = f + j * H;
        int i = i0 + r;
        sax[r] = (i < N_NODES) ? g_ax[i] : make_float4(0.f, 0.f, 0.f, 0.f);
    }
    __syncthreads();
    float wc = Wc1[f], wl = Wl1[f], b = bc1[f] + bl1[f];
    float sum = 0.f, ssq = 0.f;
    int nr = min(NPB, N_NODES - i0);
#pragma unroll 4
    for (int r = 0; r < nr; r++) {
        float4 ax = sax[r];
        float h = fmaf(ax.x, wc, fmaf(ax.y, wl, b));
        h = fmaxf(h, 0.f);
        g_h1s[(size_t)(i0 + r) * H + f] = __float2half_rn(ax.z * h);
        sum += h;
        ssq += h * h;
    }
    atomicAdd(&g_acc[OFF_BN1 + f], sum);
    atomicAdd(&g_acc[OFF_BN1 + H + f], ssq);
}

// ---------------- layer 2 aggregation (warp per node, 4-wide unroll) ----------------

__global__ void k_gather2() {
    int node = (blockIdx.x * blockDim.x + threadIdx.x) >> 5;
    int lane = threadIdx.x & 31;
    if (node >= N_NODES) return;
    int e0 = node * CAP;
    int e1 = e0 + g_deg[node];
    float ax = 0.f, ay = 0.f, az = 0.f, aw = 0.f;
    int e = e0;
    for (; e + 4 <= e1; e += 4) {
        int s0 = __ldg(&g_csrc[e]);
        int s1 = __ldg(&g_csrc[e + 1]);
        int s2 = __ldg(&g_csrc[e + 2]);
        int s3 = __ldg(&g_csrc[e + 3]);
        uint2 v0 = *(const uint2*)(g_h1s + (size_t)s0 * H + lane * 4);
        uint2 v1 = *(const uint2*)(g_h1s + (size_t)s1 * H + lane * 4);
        uint2 v2 = *(const uint2*)(g_h1s + (size_t)s2 * H + lane * 4);
        uint2 v3 = *(const uint2*)(g_h1s + (size_t)s3 * H + lane * 4);
        float2 a0 = __half22float2(*(__half2*)&v0.x), b0 = __half22float2(*(__half2*)&v0.y);
        float2 a1 = __half22float2(*(__half2*)&v1.x), b1 = __half22float2(*(__half2*)&v1.y);
        float2 a2 = __half22float2(*(__half2*)&v2.x), b2 = __half22float2(*(__half2*)&v2.y);
        float2 a3 = __half22float2(*(__half2*)&v3.x), b3 = __half22float2(*(__half2*)&v3.y);
        ax += (a0.x + a1.x) + (a2.x + a3.x);
        ay += (a0.y + a1.y) + (a2.y + a3.y);
        az += (b0.x + b1.x) + (b2.x + b3.x);
        aw += (b0.y + b1.y) + (b2.y + b3.y);
    }
    for (; e < e1; e++) {
        int s = __ldg(&g_csrc[e]);
        uint2 v = *(const uint2*)(g_h1s + (size_t)s * H + lane * 4);
        float2 f0 = __half22float2(*(__half2*)&v.x);
        float2 f1 = __half22float2(*(__half2*)&v.y);
        ax += f0.x; ay += f0.y; az += f1.x; aw += f1.y;
    }
    __half2 o0 = __floats2half2_rn(ax, ay);
    __half2 o1 = __floats2half2_rn(az, aw);
    uint2 out;
    out.x = *(uint32_t*)&o0;
    out.y = *(uint32_t*)&o1;
    *(uint2*)(g_aggh + (size_t)node * H + lane * 4) = out;
}

// ---------------- W prep: interleaved bf16 hi/lo split ----------------

__device__ __forceinline__ uint32_t pack_bf2(__nv_bfloat16 a, __nv_bfloat16 b) {
    __nv_bfloat162 p; p.x = a; p.y = b;
    return *(uint32_t*)&p;
}

__global__ void k_wprep(const float* __restrict__ Wc2, const float* __restrict__ Wl2) {
    int idx = blockIdx.x * blockDim.x + threadIdx.x;   // 128 n * 128 kwords
    if (idx >= 128 * 128) return;
    int n = idx >> 7, kw = idx & 127;
    int k0 = kw * 2, k1 = kw * 2 + 1;
    float v0 = (k0 < 128) ? Wc2[k0 * 128 + n] : Wl2[(k0 - 128) * 128 + n];
    float v1 = (k1 < 128) ? Wc2[k1 * 128 + n] : Wl2[(k1 - 128) * 128 + n];
    __nv_bfloat16 h0 = __float2bfloat16_rn(v0);
    __nv_bfloat16 h1v = __float2bfloat16_rn(v1);
    __nv_bfloat16 l0 = __float2bfloat16_rn(v0 - __bfloat162float(h0));
    __nv_bfloat16 l1 = __float2bfloat16_rn(v1 - __bfloat162float(h1v));
    g_w2[n * 128 + kw] = make_uint2(pack_bf2(h0, h1v), pack_bf2(l0, l1));
}

// ---------------- fused layer-2 GEMM (split-bf16 mma) + BN2 + pool ----------------
// 256 threads: 8 warps = 2 M-pairs x 4 N-quarters. Tile: 64 nodes x 128 feats.

#define AST 36                     // A row stride in b32 (64 bf16 + pad)
#define HST 132                    // sH row stride in f32

#define MMA3(cc, ah, al, bh0, bh1, bl0, bl1)                                   \
    asm volatile("mma.sync.aligned.m16n8k16.row.col.f32.bf16.bf16.f32 "        \
        "{%0,%1,%2,%3}, {%4,%5,%6,%7}, {%8,%9}, {%0,%1,%2,%3};"                \
        : "+f"(cc[0]), "+f"(cc[1]), "+f"(cc[2]), "+f"(cc[3])                   \
        : "r"(ah[0]), "r"(ah[1]), "r"(ah[2]), "r"(ah[3]), "r"(bh0), "r"(bh1)); \
    asm volatile("mma.sync.aligned.m16n8k16.row.col.f32.bf16.bf16.f32 "        \
        "{%0,%1,%2,%3}, {%4,%5,%6,%7}, {%8,%9}, {%0,%1,%2,%3};"                \
        : "+f"(cc[0]), "+f"(cc[1]), "+f"(cc[2]), "+f"(cc[3])                   \
        : "r"(al[0]), "r"(al[1]), "r"(al[2]), "r"(al[3]), "r"(bh0), "r"(bh1)); \
    asm volatile("mma.sync.aligned.m16n8k16.row.col.f32.bf16.bf16.f32 "        \
        "{%0,%1,%2,%3}, {%4,%5,%6,%7}, {%8,%9}, {%0,%1,%2,%3};"                \
        : "+f"(cc[0]), "+f"(cc[1]), "+f"(cc[2]), "+f"(cc[3])                   \
        : "r"(ah[0]), "r"(ah[1]), "r"(ah[2]), "r"(ah[3]), "r"(bl0), "r"(bl1));

__global__ void __launch_bounds__(256) k_gemm2(const float* __restrict__ bc2,
                                               const float* __restrict__ bl2,
                                               const int* __restrict__ bat,
                                               const float* __restrict__ g1,
                                               const float* __restrict__ be1) {
    __shared__ __align__(16) char smem_raw[64 * HST * 4];       // 33792 B union
    uint32_t* sAhi = (uint32_t*)smem_raw;                       // [64][AST]
    uint32_t* sAlo = sAhi + 64 * AST;
    __nv_bfloat16* sAhi_b = (__nv_bfloat16*)sAhi;
    __nv_bfloat16* sAlo_b = (__nv_bfloat16*)sAlo;
    float* sH = (float*)smem_raw;                               // overlay after mma
    __shared__ float ss1[H], st1[H];
    __shared__ int sb[64];
    __shared__ float sbn[256], sbq[256];

    int tid = threadIdx.x;
    int lane = tid & 31;
    int warp = tid >> 5;
    int g = lane >> 2, tg = lane & 3;
    int wx = warp & 3, wy = warp >> 2;      // wx: N-quarter, wy: M-pair
    int i0 = blockIdx.x * 64;

    if (tid < H) {   // inline BN1 finalize
        float inv_n = 1.0f / (float)N_NODES;
        float mu = g_acc[OFF_BN1 + tid] * inv_n;
        float var = g_acc[OFF_BN1 + H + tid] * inv_n - mu * mu;
        float s = g1[tid] * rsqrtf(var + EPSBN);
        ss1[tid] = s;
        st1[tid] = be1[tid] - mu * s;
    }
    if (tid < 64) {
        int i = i0 + tid;
        sb[tid] = (i < N_NODES) ? bat[i] : 0;
    }

    // staging thread mapping: row = tid>>2 (0..63), 16-col quarter = (tid&3)*16
    int srow = tid >> 2;
    int sq = (tid & 3) * 16;
    int si = i0 + srow;
    bool svalid = si < N_NODES;
    float srd = 0.f, sdi = 0.f, ssd = 0.f;
    if (svalid) { srd = g_rdinv[si]; sdi = g_dinv[si]; ssd = g_sdin[si]; }

    float c[2][4][4];
#pragma unroll
    for (int mi = 0; mi < 2; mi++)
#pragma unroll
        for (int jj = 0; jj < 4; jj++)
#pragma unroll
            for (int q = 0; q < 4; q++) c[mi][jj][q] = 0.f;

    for (int ch = 0; ch < 4; ch++) {
        int kc0 = ch * 64;
        __syncthreads();
        // stage A chunk, split hi/lo — vectorized uint2 (4 halves) loads/stores
        {
            int fbase = kc0 + sq;                    // global A column of first elem
            bool isA1 = fbase < 128;
            int fh = isA1 ? fbase : fbase - 128;     // feature index into h1s/aggh
            const uint2* hp = (const uint2*)(g_h1s + (size_t)si * H + fh);
            const uint2* ap = (const uint2*)(g_aggh + (size_t)si * H + fh);
            __nv_bfloat16* dsthi = sAhi_b + srow * (AST * 2) + sq;
            __nv_bfloat16* dstlo = sAlo_b + srow * (AST * 2) + sq;
#pragma unroll
            for (int j = 0; j < 4; j++) {
                float v[4] = {0.f, 0.f, 0.f, 0.f};
                if (svalid) {
                    uint2 hv = hp[j];
                    float2 f0 = __half22float2(*(__half2*)&hv.x);
                    float2 f1 = __half22float2(*(__half2*)&hv.y);
                    float hr[4] = {f0.x * srd, f0.y * srd, f1.x * srd, f1.y * srd};
                    if (isA1) {
                        uint2 av = ap[j];
                        float2 g0 = __half22float2(*(__half2*)&av.x);
                        float2 g1v = __half22float2(*(__half2*)&av.y);
                        float ag[4] = {g0.x, g0.y, g1v.x, g1v.y};
#pragma unroll
                        for (int q = 0; q < 4; q++) {
                            int f = fh + j * 4 + q;
                            float hn = fmaf(hr[q], ss1[f], st1[f]);
                            v[q] = sdi * (fmaf(ss1[f], ag[q], st1[f] * ssd) + sdi * hn);
                        }
                    } else {
#pragma unroll
                        for (int q = 0; q < 4; q++) {
                            int f = fh + j * 4 + q;
                            v[q] = fmaf(hr[q], ss1[f], st1[f]);
                        }
                    }
                }
                __nv_bfloat16 bh[4], bl[4];
#pragma unroll
                for (int q = 0; q < 4; q++) {
                    bh[q] = __float2bfloat16_rn(v[q]);
                    bl[q] = __float2bfloat16_rn(v[q] - __bfloat162float(bh[q]));
                }
                uint2 oh, ol;
                oh.x = pack_bf2(bh[0], bh[1]); oh.y = pack_bf2(bh[2], bh[3]);
                ol.x = pack_bf2(bl[0], bl[1]); ol.y = pack_bf2(bl[2], bl[3]);
                *(uint2*)(dsthi + j * 4) = oh;
                *(uint2*)(dstlo + j * 4) = ol;
            }
        }
        __syncthreads();
#pragma unroll
        for (int ks = 0; ks < 4; ks++) {
            int k0h = ks * 8;
            uint32_t ah[2][4], al[2][4];
#pragma unroll
            for (int mi = 0; mi < 2; mi++) {
                int rb = wy * 32 + mi * 16;
                ah[mi][0] = sAhi[(rb + g) * AST + k0h + tg];
                ah[mi][1] = sAhi[(rb + g + 8) * AST + k0h + tg];
                ah[mi][2] = sAhi[(rb + g) * AST + k0h + tg + 4];
                ah[mi][3] = sAhi[(rb + g + 8) * AST + k0h + tg + 4];
                al[mi][0] = sAlo[(rb + g) * AST + k0h + tg];
                al[mi][1] = sAlo[(rb + g + 8) * AST + k0h + tg];
                al[mi][2] = sAlo[(rb + g) * AST + k0h + tg + 4];
                al[mi][3] = sAlo[(rb + g + 8) * AST + k0h + tg + 4];
            }
#pragma unroll
            for (int jj = 0; jj < 4; jj++) {
                int n = (wx * 4 + jj) * 8 + g;
                const uint2* wp = g_w2 + n * 128 + ch * 32 + k0h + tg;
                uint2 b0 = wp[0];
                uint2 b1 = wp[4];
#pragma unroll
                for (int mi = 0; mi < 2; mi++) {
                    MMA3(c[mi][jj], ah[mi], al[mi], b0.x, b1.x, b0.y, b1.y);
                }
            }
        }
    }
    __syncthreads();
#pragma unroll
    for (int mi = 0; mi < 2; mi++) {
#pragma unroll
        for (int jj = 0; jj < 4; jj++) {
            int row = wy * 32 + mi * 16 + g;
            int col = (wx * 4 + jj) * 8 + tg * 2;
            *(float2*)&sH[row * HST + col]       = make_float2(c[mi][jj][0], c[mi][jj][1]);
            *(float2*)&sH[(row + 8) * HST + col] = make_float2(c[mi][jj][2], c[mi][jj][3]);
        }
    }
    __syncthreads();
    // epilogue: bias + BN2 stats + run-length pool; rows split across thread halves
    int t = tid & 127;
    int half = tid >> 7;
    float b = bc2[t] + bl2[t];
    int nrows = min(64, N_NODES - i0);
    int r0 = half * 32;
    int r1 = min(nrows, r0 + 32);
    float sum = 0.f, ssq = 0.f, seg = 0.f;
    int cg = (r0 < nrows) ? sb[r0] : 0;
    for (int r = r0; r < r1; r++) {
        float v = sH[r * HST + t] + b;
        sum += v;
        ssq += v * v;
        int gId = sb[r];
        if (gId != cg) {
            atomicAdd(&g_acc[OFF_POOL + cg * H + t], seg);
            seg = 0.f;
            cg = gId;
        }
        seg += v;
    }
    if (r0 < nrows) atomicAdd(&g_acc[OFF_POOL + cg * H + t], seg);
    sbn[tid] = sum;
    sbq[tid] = ssq;
    __syncthreads();
    if (tid < 128) {
        atomicAdd(&g_acc[OFF_BN2 + t], sbn[t] + sbn[t + 128]);
        atomicAdd(&g_acc[OFF_BN2 + H + t], sbq[t] + sbq[t + 128]);
    }
}

// ---------------- head ----------------

// inline BN2 finalize + pooled mean + classifier head
__global__ void __launch_bounds__(H) k_head(const float* __restrict__ W3,
                                            const float* __restrict__ b3,
                                            const float* __restrict__ g2,
                                            const float* __restrict__ be2,
                                            float* __restrict__ out) {
    __shared__ float sp[H];
    int g = blockIdx.x;
    int f = threadIdx.x;
    float inv_n = 1.0f / (float)N_NODES;
    float mu = g_acc[OFF_BN2 + f] * inv_n;
    float var = g_acc[OFF_BN2 + H + f] * inv_n - mu * mu;
    float s2 = g2[f] * rsqrtf(var + EPSBN);
    float t2 = be2[f] - mu * s2;
    float cnt = g_acc[OFF_GCNT + g];
    float pooled = 0.f;
    if (cnt > 0.f)
        pooled = fmaf(g_acc[OFF_POOL + g * H + f] / cnt, s2, t2);
    sp[f] = pooled;
    __syncthreads();
    if (f < N_CLASSES) {
        float o = b3[f];
#pragma unroll 8
        for (int k = 0; k < H; k++) o = fmaf(sp[k], W3[k * N_CLASSES + f], o);
        out[g * N_CLASSES + f] = o;
    }
}

// ---------------- host launch ----------------
extern "C" void kernel_launch(void* const* d_in, const int* in_sizes, int n_in,
                              void* d_out, int out_size) {
    const float* x   = (const float*)d_in[0];
    const int*   ei  = (const int*)d_in[1];
    const int*   bat = (const int*)d_in[2];
    const float* Wc1 = (const float*)d_in[3];
    const float* bc1 = (const float*)d_in[4];
    const float* Wl1 = (const float*)d_in[5];
    const float* bl1 = (const float*)d_in[6];
    const float* g1  = (const float*)d_in[7];
    const float* be1 = (const float*)d_in[8];
    const float* Wc2 = (const float*)d_in[9];
    const float* bc2 = (const float*)d_in[10];
    const float* Wl2 = (const float*)d_in[11];
    const float* bl2 = (const float*)d_in[12];
    const float* g2  = (const float*)d_in[13];
    const float* be2 = (const float*)d_in[14];
    const float* W3  = (const float*)d_in[15];
    const float* b3  = (const float*)d_in[16];
    float* out = (float*)d_out;

    const int* src = ei;
    const int* dst = ei + N_EDGES;

    void *p_cur, *p_acc;
    cudaGetSymbolAddress(&p_cur, g_cur);
    cudaGetSymbolAddress(&p_acc, g_acc);

    cudaMemsetAsync(p_cur, 0, N_NODES * sizeof(int), 0);
    cudaMemsetAsync(p_acc, 0, ACC_LEN * sizeof(float), 0);

    k_fill<<<(N_EDGES + 255) / 256, 256>>>(src, dst);
    k_finoff<<<(N_NODES + 1023) / 1024, 1024>>>(x, bat);
    k_gather1<<<((size_t)N_NODES * 32 + 255) / 256, 256>>>(x);
    k_layer1<<<(N_NODES + NPB - 1) / NPB, H>>>(Wc1, bc1, Wl1, bl1);
    k_wprep<<<(128 * 128 + 255) / 256, 256>>>(Wc2, Wl2);
    k_gather2<<<((size_t)N_NODES * 32 + 255) / 256, 256>>>();
    k_gemm2<<<(N_NODES + 63) / 64, 256>>>(bc2, bl2, bat, g1, be1);
    k_head<<<N_GRAPHS, H>>>(W3, b3, g2, be2, out);
}